// round 4
// baseline (speedup 1.0000x reference)
#include <cuda_runtime.h>
#include <cuda_bf16.h>

#define NN   100000
#define NPAD 100096
#define EMAX 1600000
#define D    64

// ---------------- scratch (static device globals; no allocation) ----------------
__device__ float g_buf1[NPAD * D];
__device__ float g_buf2[NPAD * D];
__device__ float g_mean[NPAD * D];
__device__ int   g_csr[EMAX];
__device__ int   g_rowptr[NN + 1];
__device__ int   g_cnt[NN];
__device__ int   g_cursor[NN];
__device__ float g_rdeg[NN];
__device__ int   g_is64;

// ---------------- dtype probe: int64 edge_index has zero high-words ----------------
__global__ void k_detect(const int* __restrict__ ei32) {
    int t = threadIdx.x;                 // 32 threads
    int v = ei32[2 * t + 1];             // odd words of first 64 (safe either dtype)
    unsigned m = __ballot_sync(0xffffffffu, v == 0);
    if (t == 0) g_is64 = (m == 0xffffffffu) ? 1 : 0;
}

// ---------------- CSR build ----------------
__global__ void k_zero() {
    int i = blockIdx.x * 256 + threadIdx.x;
    if (i < NN) g_cnt[i] = 0;
}

__device__ __forceinline__ int load_idx(const void* ei, size_t pos, int is64) {
    if (is64) return (int)((const long long*)ei)[pos];
    return ((const int*)ei)[pos];
}

__global__ void k_deg(const void* __restrict__ ei, int E) {
    int e = blockIdx.x * 256 + threadIdx.x;
    if (e < E) {
        int dst = load_idx(ei, (size_t)E + e, g_is64);
        atomicAdd(&g_cnt[dst], 1);
    }
}

// single-block exclusive scan over 100K counters; also rdeg + cursor init
__global__ void k_scan() {
    __shared__ int tmp[1024];
    int t = threadIdx.x;
    const int CH = (NN + 1023) / 1024;  // 98
    int beg = t * CH;
    int end = min(beg + CH, NN);
    int s = 0;
    for (int i = beg; i < end; i++) s += g_cnt[i];
    tmp[t] = s;
    __syncthreads();
    for (int off = 1; off < 1024; off <<= 1) {
        int add = (t >= off) ? tmp[t - off] : 0;
        __syncthreads();
        tmp[t] += add;
        __syncthreads();
    }
    int run = tmp[t] - s;  // exclusive prefix
    for (int i = beg; i < end; i++) {
        int c = g_cnt[i];
        g_rowptr[i] = run;
        g_cursor[i] = run;
        g_rdeg[i] = 1.0f / (float)max(c, 1);
        run += c;
    }
    if (t == 1023) g_rowptr[NN] = run;
}

__global__ void k_fill(const void* __restrict__ ei, int E) {
    int e = blockIdx.x * 256 + threadIdx.x;
    if (e < E) {
        int is64 = g_is64;
        int src = load_idx(ei, (size_t)e, is64);
        int dst = load_idx(ei, (size_t)E + e, is64);
        int pos = atomicAdd(&g_cursor[dst], 1);
        g_csr[pos] = src;
    }
}

// ---------------- aggregation: one warp per dst node, gather-only ----------------
// srcsel: 0 = external x, 1 = g_buf1, 2 = g_buf2
__global__ void __launch_bounds__(256) k_agg(const float* __restrict__ xin, int srcsel) {
    const float* h = (srcsel == 0) ? xin : (srcsel == 1) ? g_buf1 : g_buf2;
    int w = blockIdx.x * 8 + (threadIdx.x >> 5);
    if (w >= NN) return;
    int lane = threadIdx.x & 31;
    int beg = g_rowptr[w];
    int end = g_rowptr[w + 1];
    const float2* hp = (const float2*)h;

    float ax0 = 0.f, ay0 = 0.f, ax1 = 0.f, ay1 = 0.f;
    float ax2 = 0.f, ay2 = 0.f, ax3 = 0.f, ay3 = 0.f;
    int j = beg;
    for (; j + 4 <= end; j += 4) {
        int s0 = g_csr[j];
        int s1 = g_csr[j + 1];
        int s2 = g_csr[j + 2];
        int s3 = g_csr[j + 3];
        float2 v0 = __ldg(hp + s0 * 32 + lane);
        float2 v1 = __ldg(hp + s1 * 32 + lane);
        float2 v2 = __ldg(hp + s2 * 32 + lane);
        float2 v3 = __ldg(hp + s3 * 32 + lane);
        ax0 += v0.x; ay0 += v0.y;
        ax1 += v1.x; ay1 += v1.y;
        ax2 += v2.x; ay2 += v2.y;
        ax3 += v3.x; ay3 += v3.y;
    }
    for (; j < end; j++) {
        int s = g_csr[j];
        float2 v = __ldg(hp + s * 32 + lane);
        ax0 += v.x; ay0 += v.y;
    }
    float rd = g_rdeg[w];
    float2 r;
    r.x = ((ax0 + ax1) + (ax2 + ax3)) * rd;
    r.y = ((ay0 + ay1) + (ay2 + ay3)) * rd;
    ((float2*)g_mean)[w * 32 + lane] = r;
}

// ---------------- fused dual-GEMM: out = h@Ws + mean@Wn + b (opt relu) ----------------
// 64 nodes per block, 256 threads: thread = (node, quarter), 16 cols each = 8 f32x2 accs.
// Static shared only (33 KB): transposed feature tile (65-pad) + weight tile.
// fp32 packed FMA (fma.rn.f32x2) doubles fp32 MAC throughput on sm_103a.
template <bool RELU>
__global__ void __launch_bounds__(256) k_gemm(const float* __restrict__ xin,
                                              const float* __restrict__ Ws,
                                              const float* __restrict__ Wn,
                                              const float* __restrict__ bias,
                                              float* __restrict__ outp,
                                              int srcsel, int dstsel) {
    __shared__ float sh_t[64 * 65];   // [k][node], padded
    __shared__ float sw[64 * 64];     // [k][col]

    const float* hin = (srcsel == 0) ? xin : (srcsel == 1) ? g_buf1 : g_buf2;
    float* out = (dstsel == 0) ? outp : (dstsel == 1) ? g_buf1 : g_buf2;

    int t = threadIdx.x;
    int base = blockIdx.x * 64;

    unsigned long long acc[8];
#pragma unroll
    for (int i = 0; i < 8; i++) acc[i] = 0ull;

    int node = t >> 2;   // 0..63
    int q = t & 3;       // 0..3 (16 cols each)

    for (int p = 0; p < 2; p++) {
        const float* src = (p == 0) ? hin : g_mean;
        const float* W = (p == 0) ? Ws : Wn;
        if (p) __syncthreads();  // previous compute done before overwriting tiles

        // weights: 1024 float4s
#pragma unroll
        for (int i = 0; i < 4; i++) {
            int idx = t + i * 256;
            ((float4*)sw)[idx] = ((const float4*)W)[idx];
        }
        // feature tile: 64 rows x 64 cols, store transposed into sh_t[k*65+node]
#pragma unroll
        for (int i = 0; i < 4; i++) {
            int idx = t + i * 256;
            int row = idx >> 4;
            int c4 = idx & 15;
            float4 v;
            if (base + row < NN) {
                v = ((const float4*)(src + (size_t)(base + row) * 64))[c4];
            } else {
                v.x = v.y = v.z = v.w = 0.f;
            }
            int kc = c4 * 4;
            sh_t[(kc + 0) * 65 + row] = v.x;
            sh_t[(kc + 1) * 65 + row] = v.y;
            sh_t[(kc + 2) * 65 + row] = v.z;
            sh_t[(kc + 3) * 65 + row] = v.w;
        }
        __syncthreads();

#pragma unroll 8
        for (int k = 0; k < 64; k++) {
            float a = sh_t[k * 65 + node];
            unsigned long long a2;
            asm("mov.b64 %0, {%1, %1};" : "=l"(a2) : "f"(a));
            const ulonglong2* wr = (const ulonglong2*)(sw + k * 64 + q * 16);
#pragma unroll
            for (int i = 0; i < 4; i++) {
                ulonglong2 w = wr[i];
                asm("fma.rn.f32x2 %0, %1, %2, %0;" : "+l"(acc[2 * i]) : "l"(w.x), "l"(a2));
                asm("fma.rn.f32x2 %0, %1, %2, %0;" : "+l"(acc[2 * i + 1]) : "l"(w.y), "l"(a2));
            }
        }
    }

    int g = base + node;
    if (g < NN) {
        float* op = out + (size_t)g * 64 + q * 16;
        const float* bp = bias + q * 16;
#pragma unroll
        for (int i = 0; i < 4; i++) {
            float v0, v1, v2, v3;
            asm("mov.b64 {%0, %1}, %2;" : "=f"(v0), "=f"(v1) : "l"(acc[2 * i]));
            asm("mov.b64 {%0, %1}, %2;" : "=f"(v2), "=f"(v3) : "l"(acc[2 * i + 1]));
            v0 += __ldg(bp + 4 * i + 0);
            v1 += __ldg(bp + 4 * i + 1);
            v2 += __ldg(bp + 4 * i + 2);
            v3 += __ldg(bp + 4 * i + 3);
            if (RELU) {
                v0 = fmaxf(v0, 0.f); v1 = fmaxf(v1, 0.f);
                v2 = fmaxf(v2, 0.f); v3 = fmaxf(v3, 0.f);
            }
            float4 o;
            o.x = v0; o.y = v1; o.z = v2; o.w = v3;
            ((float4*)op)[i] = o;
        }
    }
}

// ---------------- launch: kernel launches ONLY (graph-capture safe) ----------------
extern "C" void kernel_launch(void* const* d_in, const int* in_sizes, int n_in,
                              void* d_out, int out_size) {
    const float* x = (const float*)d_in[0];
    const void* ei = d_in[1];
    const float* ws1 = (const float*)d_in[2];
    const float* wn1 = (const float*)d_in[3];
    const float* b1  = (const float*)d_in[4];
    const float* ws2 = (const float*)d_in[5];
    const float* wn2 = (const float*)d_in[6];
    const float* b2  = (const float*)d_in[7];
    const float* ws3 = (const float*)d_in[8];
    const float* wn3 = (const float*)d_in[9];
    const float* b3  = (const float*)d_in[10];
    float* out = (float*)d_out;

    int E = in_sizes[1] / 2;   // element count / 2, dtype-independent

    int eb = (E + 255) / 256;
    int aggBlocks = (NN + 7) / 8;        // warp per node
    int gemmBlocks = (NN + 63) / 64;     // 1563

    // dtype probe + CSR build (per call; deterministic up to csr ordering)
    k_detect<<<1, 32>>>((const int*)ei);
    k_zero<<<(NN + 255) / 256, 256>>>();
    k_deg<<<eb, 256>>>(ei, E);
    k_scan<<<1, 1024>>>();
    k_fill<<<eb, 256>>>(ei, E);

    // layer 1: x -> g_buf1
    k_agg<<<aggBlocks, 256>>>(x, 0);
    k_gemm<true><<<gemmBlocks, 256>>>(x, ws1, wn1, b1, out, 0, 1);
    // layer 2: g_buf1 -> g_buf2
    k_agg<<<aggBlocks, 256>>>(x, 1);
    k_gemm<true><<<gemmBlocks, 256>>>(x, ws2, wn2, b2, out, 1, 2);
    // layer 3: g_buf2 -> out
    k_agg<<<aggBlocks, 256>>>(x, 2);
    k_gemm<false><<<gemmBlocks, 256>>>(x, ws3, wn3, b3, out, 2, 0);
}

// round 5
// speedup vs baseline: 1.2904x; 1.2904x over previous
#include <cuda_runtime.h>
#include <cuda_bf16.h>

#define NN   100000
#define NPAD 100096
#define EMAX 1600000
#define D    64

#define SCAN_CHUNK  512
#define SCAN_BLOCKS ((NN + SCAN_CHUNK - 1) / SCAN_CHUNK)   // 196

// ---------------- scratch (static device globals; no allocation) ----------------
__device__ float g_buf1[NPAD * D];
__device__ float g_buf2[NPAD * D];
__device__ float g_mean[NPAD * D];
__device__ int   g_csr[EMAX];
__device__ int   g_rowptr[NN + 1];
__device__ int   g_cnt[NN];
__device__ int   g_cursor[NN];
__device__ float g_rdeg[NN];
__device__ int   g_is64;
__device__ int   g_bsum[SCAN_BLOCKS];
__device__ int   g_boff[SCAN_BLOCKS];

// ---------------- dtype probe: int64 edge_index has zero high-words ----------------
__global__ void k_detect(const int* __restrict__ ei32) {
    int t = threadIdx.x;                 // 32 threads
    int v = ei32[2 * t + 1];             // odd words of first 64 (safe either dtype)
    unsigned m = __ballot_sync(0xffffffffu, v == 0);
    if (t == 0) g_is64 = (m == 0xffffffffu) ? 1 : 0;
}

// ---------------- CSR build ----------------
__global__ void k_zero() {
    int i = blockIdx.x * 256 + threadIdx.x;
    if (i < NN) g_cnt[i] = 0;
}

__device__ __forceinline__ int load_idx(const void* ei, size_t pos, int is64) {
    if (is64) return (int)__ldg((const long long*)ei + pos);
    return __ldg((const int*)ei + pos);
}

__global__ void k_deg(const void* __restrict__ ei, int E) {
    int e = (blockIdx.x * 256 + threadIdx.x) * 2;
    int is64 = g_is64;
    if (e < E) atomicAdd(&g_cnt[load_idx(ei, (size_t)E + e, is64)], 1);
    if (e + 1 < E) atomicAdd(&g_cnt[load_idx(ei, (size_t)E + e + 1, is64)], 1);
}

// ---- phase 1: per-block sums (each block covers SCAN_CHUNK counters) ----
__global__ void __launch_bounds__(256) k_part() {
    int b = blockIdx.x;
    int t = threadIdx.x;
    int i0 = b * SCAN_CHUNK + t * 2;
    int s = 0;
    if (i0 < NN) s += g_cnt[i0];
    if (i0 + 1 < NN) s += g_cnt[i0 + 1];
#pragma unroll
    for (int off = 1; off < 32; off <<= 1) {
        int n = __shfl_down_sync(0xffffffffu, s, off);
        s += n;
    }
    __shared__ int wsum[8];
    if ((t & 31) == 0) wsum[t >> 5] = s;
    __syncthreads();
    if (t == 0) {
        int tot = 0;
#pragma unroll
        for (int w = 0; w < 8; w++) tot += wsum[w];
        g_bsum[b] = tot;
    }
}

// ---- phase 2: exclusive scan of 196 block sums (1 block) ----
__global__ void __launch_bounds__(256) k_bscan() {
    int t = threadIdx.x;
    int v = (t < SCAN_BLOCKS) ? g_bsum[t] : 0;
    int s = v;
#pragma unroll
    for (int off = 1; off < 32; off <<= 1) {
        int n = __shfl_up_sync(0xffffffffu, s, off);
        if ((t & 31) >= off) s += n;
    }
    __shared__ int wsum[8];
    if ((t & 31) == 31) wsum[t >> 5] = s;
    __syncthreads();
    int add = 0;
#pragma unroll
    for (int w = 0; w < 8; w++)
        if (w < (t >> 5)) add += wsum[w];
    int incl = s + add;
    if (t < SCAN_BLOCKS) g_boff[t] = incl - v;   // exclusive
    if (t == SCAN_BLOCKS - 1) g_rowptr[NN] = incl;
}

// ---- phase 3: local scan + apply (rowptr / cursor / rdeg) ----
__global__ void __launch_bounds__(256) k_apply() {
    int b = blockIdx.x;
    int t = threadIdx.x;
    int i0 = b * SCAN_CHUNK + t * 2;
    int c0 = (i0 < NN) ? g_cnt[i0] : 0;
    int c1 = (i0 + 1 < NN) ? g_cnt[i0 + 1] : 0;
    int s = c0 + c1;
    int incl = s;
#pragma unroll
    for (int off = 1; off < 32; off <<= 1) {
        int n = __shfl_up_sync(0xffffffffu, incl, off);
        if ((t & 31) >= off) incl += n;
    }
    __shared__ int wsum[8];
    if ((t & 31) == 31) wsum[t >> 5] = incl;
    __syncthreads();
    int add = 0;
#pragma unroll
    for (int w = 0; w < 8; w++)
        if (w < (t >> 5)) add += wsum[w];
    int run = g_boff[b] + incl + add - s;   // exclusive prefix for i0
    if (i0 < NN) {
        g_rowptr[i0] = run;
        g_cursor[i0] = run;
        g_rdeg[i0] = 1.0f / (float)max(c0, 1);
        run += c0;
    }
    if (i0 + 1 < NN) {
        g_rowptr[i0 + 1] = run;
        g_cursor[i0 + 1] = run;
        g_rdeg[i0 + 1] = 1.0f / (float)max(c1, 1);
    }
}

__global__ void k_fill(const void* __restrict__ ei, int E) {
    int e = (blockIdx.x * 256 + threadIdx.x) * 2;
    int is64 = g_is64;
    if (e < E) {
        int src = load_idx(ei, (size_t)e, is64);
        int dst = load_idx(ei, (size_t)E + e, is64);
        g_csr[atomicAdd(&g_cursor[dst], 1)] = src;
    }
    if (e + 1 < E) {
        int src = load_idx(ei, (size_t)e + 1, is64);
        int dst = load_idx(ei, (size_t)E + e + 1, is64);
        g_csr[atomicAdd(&g_cursor[dst], 1)] = src;
    }
}

// ---------------- aggregation: warp per dst node, 2 rows per iter (float4) ----------------
// srcsel: 0 = external x, 1 = g_buf1, 2 = g_buf2
__global__ void __launch_bounds__(256) k_agg(const float* __restrict__ xin, int srcsel) {
    const float* h = (srcsel == 0) ? xin : (srcsel == 1) ? g_buf1 : g_buf2;
    int w = blockIdx.x * 8 + (threadIdx.x >> 5);
    if (w >= NN) return;
    int lane = threadIdx.x & 31;
    int sub = lane >> 4;     // which of 2 edges this iter
    int c = lane & 15;       // 16B chunk within row
    int beg = g_rowptr[w];
    int end = g_rowptr[w + 1];
    const float4* hp = (const float4*)h;

    float ax0 = 0.f, ay0 = 0.f, az0 = 0.f, aw0 = 0.f;
    float ax1 = 0.f, ay1 = 0.f, az1 = 0.f, aw1 = 0.f;
    int j = beg + sub;
    for (; j + 2 < end; j += 4) {
        int s0 = g_csr[j];
        int s1 = g_csr[j + 2];
        float4 v0 = __ldg(hp + s0 * 16 + c);
        float4 v1 = __ldg(hp + s1 * 16 + c);
        ax0 += v0.x; ay0 += v0.y; az0 += v0.z; aw0 += v0.w;
        ax1 += v1.x; ay1 += v1.y; az1 += v1.z; aw1 += v1.w;
    }
    if (j < end) {
        float4 v = __ldg(hp + g_csr[j] * 16 + c);
        ax0 += v.x; ay0 += v.y; az0 += v.z; aw0 += v.w;
    }
    float x = ax0 + ax1, y = ay0 + ay1, z = az0 + az1, ww = aw0 + aw1;
    x += __shfl_xor_sync(0xffffffffu, x, 16);
    y += __shfl_xor_sync(0xffffffffu, y, 16);
    z += __shfl_xor_sync(0xffffffffu, z, 16);
    ww += __shfl_xor_sync(0xffffffffu, ww, 16);
    if (sub == 0) {
        float rd = g_rdeg[w];
        float4 r;
        r.x = x * rd; r.y = y * rd; r.z = z * rd; r.w = ww * rd;
        ((float4*)g_mean)[w * 16 + c] = r;
    }
}

// ---------------- fused dual-GEMM: out = h@Ws + mean@Wn + b (opt relu) ----------------
// 64 nodes per block, 256 threads: thread = (node, quarter), 16 cols each = 8 f32x2 accs.
// Static shared only (33 KB): transposed feature tile (65-pad) + weight tile.
// fp32 packed FMA (fma.rn.f32x2) doubles fp32 MAC throughput on sm_103a.
template <bool RELU>
__global__ void __launch_bounds__(256) k_gemm(const float* __restrict__ xin,
                                              const float* __restrict__ Ws,
                                              const float* __restrict__ Wn,
                                              const float* __restrict__ bias,
                                              float* __restrict__ outp,
                                              int srcsel, int dstsel) {
    __shared__ float sh_t[64 * 65];   // [k][node], padded
    __shared__ float sw[64 * 64];     // [k][col]

    const float* hin = (srcsel == 0) ? xin : (srcsel == 1) ? g_buf1 : g_buf2;
    float* out = (dstsel == 0) ? outp : (dstsel == 1) ? g_buf1 : g_buf2;

    int t = threadIdx.x;
    int base = blockIdx.x * 64;

    unsigned long long acc[8];
#pragma unroll
    for (int i = 0; i < 8; i++) acc[i] = 0ull;

    int node = t >> 2;   // 0..63
    int q = t & 3;       // 0..3 (16 cols each)

    for (int p = 0; p < 2; p++) {
        const float* src = (p == 0) ? hin : g_mean;
        const float* W = (p == 0) ? Ws : Wn;
        if (p) __syncthreads();  // previous compute done before overwriting tiles

        // weights: 1024 float4s
#pragma unroll
        for (int i = 0; i < 4; i++) {
            int idx = t + i * 256;
            ((float4*)sw)[idx] = ((const float4*)W)[idx];
        }
        // feature tile: 64 rows x 64 cols, store transposed into sh_t[k*65+node]
#pragma unroll
        for (int i = 0; i < 4; i++) {
            int idx = t + i * 256;
            int row = idx >> 4;
            int c4 = idx & 15;
            float4 v;
            if (base + row < NN) {
                v = ((const float4*)(src + (size_t)(base + row) * 64))[c4];
            } else {
                v.x = v.y = v.z = v.w = 0.f;
            }
            int kc = c4 * 4;
            sh_t[(kc + 0) * 65 + row] = v.x;
            sh_t[(kc + 1) * 65 + row] = v.y;
            sh_t[(kc + 2) * 65 + row] = v.z;
            sh_t[(kc + 3) * 65 + row] = v.w;
        }
        __syncthreads();

#pragma unroll 8
        for (int k = 0; k < 64; k++) {
            float a = sh_t[k * 65 + node];
            unsigned long long a2;
            asm("mov.b64 %0, {%1, %1};" : "=l"(a2) : "f"(a));
            const ulonglong2* wr = (const ulonglong2*)(sw + k * 64 + q * 16);
#pragma unroll
            for (int i = 0; i < 4; i++) {
                ulonglong2 w = wr[i];
                asm("fma.rn.f32x2 %0, %1, %2, %0;" : "+l"(acc[2 * i]) : "l"(w.x), "l"(a2));
                asm("fma.rn.f32x2 %0, %1, %2, %0;" : "+l"(acc[2 * i + 1]) : "l"(w.y), "l"(a2));
            }
        }
    }

    int g = base + node;
    if (g < NN) {
        float* op = out + (size_t)g * 64 + q * 16;
        const float* bp = bias + q * 16;
#pragma unroll
        for (int i = 0; i < 4; i++) {
            float v0, v1, v2, v3;
            asm("mov.b64 {%0, %1}, %2;" : "=f"(v0), "=f"(v1) : "l"(acc[2 * i]));
            asm("mov.b64 {%0, %1}, %2;" : "=f"(v2), "=f"(v3) : "l"(acc[2 * i + 1]));
            v0 += __ldg(bp + 4 * i + 0);
            v1 += __ldg(bp + 4 * i + 1);
            v2 += __ldg(bp + 4 * i + 2);
            v3 += __ldg(bp + 4 * i + 3);
            if (RELU) {
                v0 = fmaxf(v0, 0.f); v1 = fmaxf(v1, 0.f);
                v2 = fmaxf(v2, 0.f); v3 = fmaxf(v3, 0.f);
            }
            float4 o;
            o.x = v0; o.y = v1; o.z = v2; o.w = v3;
            ((float4*)op)[i] = o;
        }
    }
}

// ---------------- launch: kernel launches ONLY (graph-capture safe) ----------------
extern "C" void kernel_launch(void* const* d_in, const int* in_sizes, int n_in,
                              void* d_out, int out_size) {
    const float* x = (const float*)d_in[0];
    const void* ei = d_in[1];
    const float* ws1 = (const float*)d_in[2];
    const float* wn1 = (const float*)d_in[3];
    const float* b1  = (const float*)d_in[4];
    const float* ws2 = (const float*)d_in[5];
    const float* wn2 = (const float*)d_in[6];
    const float* b2  = (const float*)d_in[7];
    const float* ws3 = (const float*)d_in[8];
    const float* wn3 = (const float*)d_in[9];
    const float* b3  = (const float*)d_in[10];
    float* out = (float*)d_out;

    int E = in_sizes[1] / 2;   // element count / 2, dtype-independent

    int eb2 = (E / 2 + 255) / 256;       // 2 edges per thread
    int aggBlocks = (NN + 7) / 8;        // warp per node
    int gemmBlocks = (NN + 63) / 64;     // 1563

    // dtype probe + CSR build (per call; deterministic up to csr ordering)
    k_detect<<<1, 32>>>((const int*)ei);
    k_zero<<<(NN + 255) / 256, 256>>>();
    k_deg<<<eb2, 256>>>(ei, E);
    k_part<<<SCAN_BLOCKS, 256>>>();
    k_bscan<<<1, 256>>>();
    k_apply<<<SCAN_BLOCKS, 256>>>();
    k_fill<<<eb2, 256>>>(ei, E);

    // layer 1: x -> g_buf1
    k_agg<<<aggBlocks, 256>>>(x, 0);
    k_gemm<true><<<gemmBlocks, 256>>>(x, ws1, wn1, b1, out, 0, 1);
    // layer 2: g_buf1 -> g_buf2
    k_agg<<<aggBlocks, 256>>>(x, 1);
    k_gemm<true><<<gemmBlocks, 256>>>(x, ws2, wn2, b2, out, 1, 2);
    // layer 3: g_buf2 -> out
    k_agg<<<aggBlocks, 256>>>(x, 2);
    k_gemm<false><<<gemmBlocks, 256>>>(x, ws3, wn3, b3, out, 2, 0);
}